// round 16
// baseline (speedup 1.0000x reference)
#include <cuda_runtime.h>
#include <cuda_bf16.h>
#include <math.h>
#include <stdint.h>

#define TT 512
#define BB 64
#define KIN 1024
#define HH 1024
#define GG 4096   // 4*H

// ------------------------------------------------------------------
// Scratch (device globals: allocation is forbidden in kernel_launch)
// ------------------------------------------------------------------
__device__ float         g_x4[(size_t)TT * BB * GG];     // 512 MB fp32: X@Wx^T + b
__device__ __nv_bfloat16 g_xh[(size_t)TT * BB * KIN];    // X hi split
__device__ __nv_bfloat16 g_xl[(size_t)TT * BB * KIN];    // X lo split
__device__ __nv_bfloat16 g_wxh[(size_t)GG * KIN];        // Wx hi
__device__ __nv_bfloat16 g_wxl[(size_t)GG * KIN];        // Wx lo
__device__ unsigned      g_cpk[2][BB * HH];              // packed (hi<<16)|lo cell state
__device__ unsigned      g_bar;                          // grid barrier counter

// ------------------------------------------------------------------
// helpers
// ------------------------------------------------------------------
__device__ __forceinline__ unsigned pack_split(float v) {
    __nv_bfloat16 h = __float2bfloat16_rn(v);
    float r = v - __bfloat162float(h);
    __nv_bfloat16 l = __float2bfloat16_rn(r);
    return ((unsigned)__bfloat16_as_ushort(h) << 16) |
           (unsigned)__bfloat16_as_ushort(l);
}

__device__ __forceinline__ uint32_t sh_addr(const void* p) {
    return (uint32_t)__cvta_generic_to_shared(p);
}

#define LDSM_X4(r, addr)                                                     \
    asm volatile("ldmatrix.sync.aligned.m8n8.x4.shared.b16 {%0,%1,%2,%3}, [%4];" \
                 : "=r"((r)[0]), "=r"((r)[1]), "=r"((r)[2]), "=r"((r)[3])    \
                 : "r"(addr))

#define MMA_BF16(d, a, b0, b1)                                               \
    asm volatile("mma.sync.aligned.m16n8k16.row.col.f32.bf16.bf16.f32 "      \
                 "{%0,%1,%2,%3}, {%4,%5,%6,%7}, {%8,%9}, {%0,%1,%2,%3};"     \
                 : "+f"((d)[0]), "+f"((d)[1]), "+f"((d)[2]), "+f"((d)[3])    \
                 : "r"((a)[0]), "r"((a)[1]), "r"((a)[2]), "r"((a)[3]),       \
                   "r"(b0), "r"(b1))

// producer/consumer named barriers: 128 staging + 32 consumer = 160
#define BAR_SYNC160(id)                                                      \
    asm volatile("bar.sync %0, 160;" :: "r"(id) : "memory")
#define BAR_ARRIVE160(id)                                                    \
    asm volatile("bar.arrive %0, 160;" :: "r"(id) : "memory")

// ------------------------------------------------------------------
// Init: barrier + seed packed c buffer
// ------------------------------------------------------------------
__global__ void init_kernel(const float* __restrict__ c0) {
    int idx = blockIdx.x * blockDim.x + threadIdx.x;
    if (idx == 0) g_bar = 0u;
    if (idx < BB * HH) g_cpk[0][idx] = pack_split(c0[idx]);
}

// ------------------------------------------------------------------
// Split kernels: fp32 -> (hi, lo) bf16
// ------------------------------------------------------------------
__device__ __forceinline__ void split4_store(const float4* src, uint2* dh,
                                             uint2* dl, int i) {
    float4 v = src[i];
    unsigned p0 = pack_split(v.x), p1 = pack_split(v.y);
    unsigned p2 = pack_split(v.z), p3 = pack_split(v.w);
    dh[i] = make_uint2(__byte_perm(p0, p1, 0x7632), __byte_perm(p2, p3, 0x7632));
    dl[i] = make_uint2(__byte_perm(p0, p1, 0x5410), __byte_perm(p2, p3, 0x5410));
}

__global__ void split_x_kernel(const float* __restrict__ X) {
    int i = blockIdx.x * blockDim.x + threadIdx.x;
    const int n4 = TT * BB * KIN / 4;
    if (i < n4)
        split4_store((const float4*)X, (uint2*)g_xh, (uint2*)g_xl, i);
}

__global__ void split_w_kernel(const float* __restrict__ W) {
    int i = blockIdx.x * blockDim.x + threadIdx.x;
    const int n4 = GG * KIN / 4;
    if (i < n4)
        split4_store((const float4*)W, (uint2*)g_wxh, (uint2*)g_wxl, i);
}

// ------------------------------------------------------------------
// X4 GEMM via tensor cores (R6-proven, unchanged)
// ------------------------------------------------------------------
#define XTILE (128 * 72)
#define XBUF_BYTES (XTILE * 2)

extern __shared__ char smem_raw[];

__global__ void __launch_bounds__(256) x4_mma_kernel(const float* __restrict__ bias) {
    __nv_bfloat16* SA = (__nv_bfloat16*)smem_raw;
    __nv_bfloat16* SB = SA + 2 * XTILE;

    const int tid  = threadIdx.x;
    const int lane = tid & 31;
    const int wid  = tid >> 5;
    const int wm   = wid >> 1;
    const int wn   = wid & 1;
    const int m0   = blockIdx.y * 128;
    const int n0   = blockIdx.x * 128;

    float acc[2][8][4];
#pragma unroll
    for (int mi = 0; mi < 2; ++mi)
#pragma unroll
        for (int nt = 0; nt < 8; ++nt)
#pragma unroll
            for (int e = 0; e < 4; ++e) acc[mi][nt][e] = 0.f;

    const uint32_t a_base =
        sh_addr(&SA[(wm * 32 + (lane & 15)) * 72 + (lane >> 4) * 8]);
    const uint32_t b_base =
        sh_addr(&SB[(wn * 64 + ((lane >> 4) << 3) + (lane & 7)) * 72 +
                    ((lane >> 3) & 1) * 8]);

    const int lrow = tid >> 3;
    const int lseg = tid & 7;

    uint4 av[4], bv[4];
#pragma unroll
    for (int j = 0; j < 4; ++j) {
        int row = lrow + 32 * j;
        av[j] = *(const uint4*)(g_xh  + (size_t)(m0 + row) * KIN + lseg * 8);
        bv[j] = *(const uint4*)(g_wxh + (size_t)(n0 + row) * KIN + lseg * 8);
    }
#pragma unroll
    for (int j = 0; j < 4; ++j) {
        int row = lrow + 32 * j;
        *(uint4*)&SA[row * 72 + lseg * 8] = av[j];
        *(uint4*)&SB[row * 72 + lseg * 8] = bv[j];
    }
    __syncthreads();

    for (int kc2 = 0; kc2 < 48; ++kc2) {
        const uint32_t boff = (uint32_t)((kc2 & 1) * XBUF_BYTES);

        if (kc2 < 47) {
            int nk = kc2 + 1;
            int p  = nk >> 4;
            int kb = (nk & 15) << 6;
            const __nv_bfloat16* Asrc = (p == 1) ? g_xl : g_xh;
            const __nv_bfloat16* Bsrc = (p == 2) ? g_wxl : g_wxh;
#pragma unroll
            for (int j = 0; j < 4; ++j) {
                int row = lrow + 32 * j;
                av[j] = *(const uint4*)(Asrc + (size_t)(m0 + row) * KIN + kb + lseg * 8);
                bv[j] = *(const uint4*)(Bsrc + (size_t)(n0 + row) * KIN + kb + lseg * 8);
            }
        }

#pragma unroll
        for (int ks = 0; ks < 4; ++ks) {
            uint32_t a[2][4];
            LDSM_X4(a[0], a_base + boff + (uint32_t)(ks * 16) * 2);
            LDSM_X4(a[1], a_base + boff + (uint32_t)(16 * 72 + ks * 16) * 2);
#pragma unroll
            for (int ntp = 0; ntp < 4; ++ntp) {
                uint32_t b4[4];
                LDSM_X4(b4, b_base + boff +
                            (uint32_t)(ntp * 16 * 72 + ks * 16) * 2);
#pragma unroll
                for (int mi = 0; mi < 2; ++mi) {
                    MMA_BF16(acc[mi][2 * ntp],     a[mi], b4[0], b4[1]);
                    MMA_BF16(acc[mi][2 * ntp + 1], a[mi], b4[2], b4[3]);
                }
            }
        }

        if (kc2 < 47) {
            __nv_bfloat16* SAd = SA + ((kc2 + 1) & 1) * XTILE;
            __nv_bfloat16* SBd = SB + ((kc2 + 1) & 1) * XTILE;
#pragma unroll
            for (int j = 0; j < 4; ++j) {
                int row = lrow + 32 * j;
                *(uint4*)&SAd[row * 72 + lseg * 8] = av[j];
                *(uint4*)&SBd[row * 72 + lseg * 8] = bv[j];
            }
        }
        __syncthreads();
    }

    const int r0  = m0 + wm * 32 + (lane >> 2);
    const int c0c = n0 + wn * 64 + (lane & 3) * 2;
#pragma unroll
    for (int nt = 0; nt < 8; ++nt) {
        float2 bv2 = *(const float2*)&bias[c0c + nt * 8];
#pragma unroll
        for (int mi = 0; mi < 2; ++mi) {
            float* o = g_x4 + (size_t)(r0 + mi * 16) * GG + c0c + nt * 8;
            float2 v0 = make_float2(acc[mi][nt][0] + bv2.x, acc[mi][nt][1] + bv2.y);
            float2 v1 = make_float2(acc[mi][nt][2] + bv2.x, acc[mi][nt][3] + bv2.y);
            *(float2*)o            = v0;
            *(float2*)(o + 8 * GG) = v1;
        }
    }
}

// ------------------------------------------------------------------
// Persistent recurrence kernel v5: warp-specialized + K-split MMA.
// 128 CTAs x 256 threads.
//   Warps 0-3 (MMA): each computes FULL 64x32 output over a K-quarter
//     (k64-chunks w, w+4, w+8, w+12), m64 x n32 tile -> no fragment
//     duplication (12 LDSM.X4 : 48 HMMA per k16).
//   Warps 4-7 (staging): LDG packed c -> PRMT -> STS into 4 k64 buffers.
// Buffer cc&3 is consumed exclusively by warp cc&3.
//   filled[w]:   id 1+w (staging arrive x128, warp w sync x32; count 160)
//   consumed[w]: id 5+w (warp w arrive x32, staging sync x128; count 160)
// Partial outputs parked in each warp's own (dead) buffer region; gates
// sum the 4 partials.
// ------------------------------------------------------------------
#define NCH 16                          // k64 chunks per step

// smem byte offsets
#define OFF_WHH  0                      // bf16 [32][1032]   66048
#define OFF_WHL  66048                  // bf16 [32][1032]   66048
#define OFF_CH   132096                 // 4 bufs x 64 rows x 72 bf16 = 36864
#define OFF_CL   168960                 // 4 bufs (lo)                 36864
#define OFF_HS   205824                 // float [64][8]     2048
#define OFF_CS   207872                 // float [64][8]     2048
#define RSMEM_TOTAL 209920

#define WH_ROW_B   (1032 * 2)           // 2064
#define CH_ROW_B   (72 * 2)             // 144 (k64 + 8 pad)
#define CBUF_B     (64 * CH_ROW_B)      // 9216 per buffer
#define PART_STRIDE 34                  // fp32 partial row stride (even)

__global__ void __launch_bounds__(256, 1) lstm_persistent(
    const float* __restrict__ h0, const float* __restrict__ c0,
    const int* __restrict__ mask, const float* __restrict__ Wh,
    float* __restrict__ out)
{
    const int tid   = threadIdx.x;
    const int lane  = tid & 31;
    const int w     = tid >> 5;      // warp 0..7
    const int ci    = blockIdx.x;
    const int jbase = ci * 8;

    char* sm = smem_raw;
    const uint32_t smem_base = sh_addr(sm);
    __nv_bfloat16* whH = (__nv_bfloat16*)(sm + OFF_WHH);
    __nv_bfloat16* whL = (__nv_bfloat16*)(sm + OFF_WHL);
    float* hsS  = (float*)(sm + OFF_HS);
    float* csS  = (float*)(sm + OFF_CS);

    // ---- load Wh slice, split to bf16 hi/lo (resident all steps)
    for (int i = 0; i < 128; ++i) {
        int e = i * 256 + tid;           // 32768 elements
        int n = e >> 10, k = e & 1023;
        int grow = (n >> 3) * HH + jbase + (n & 7);
        float v = Wh[(size_t)grow * HH + k];
        __nv_bfloat16 h = __float2bfloat16_rn(v);
        float r = v - __bfloat162float(h);
        whH[n * 1032 + k] = h;
        whL[n * 1032 + k] = __float2bfloat16_rn(r);
    }
    // ---- init h / own-c state
    for (int p = tid; p < 512; p += 256) {
        int b = p >> 3, jj = p & 7;
        hsS[b * 8 + jj] = h0[b * HH + jbase + jj];
        csS[b * 8 + jj] = c0[b * HH + jbase + jj];
    }
    __syncthreads();

    // ---- MMA-warp addressing (warps 0-3 own buffer w)
    const uint32_t aH_base = smem_base + OFF_CH + (uint32_t)(w & 3) * CBUF_B +
        (uint32_t)((lane & 15) * CH_ROW_B + (lane >> 4) * 16);
    const uint32_t aL_base = aH_base + (OFF_CL - OFF_CH);
    const uint32_t bH_base = smem_base + OFF_WHH +
        (uint32_t)((((lane >> 4) << 3) + (lane & 7)) * WH_ROW_B +
                   ((lane >> 3) & 1) * 16);
    const uint32_t bL_base = bH_base + (OFF_WHL - OFF_WHH);

    // ---- staging-warp addressing (warps 4-7)
    const int tid2 = tid - 128;              // 0..127
    const int sr0  = (tid2 >> 4) & 7;        // base row 0..7
    const int sk4  = tid2 & 15;              // uint4 k-index within chunk
    const uint32_t sts_off = (uint32_t)(sr0 * CH_ROW_B + sk4 * 8);

    unsigned bar_target = 0;

    // ---- prefetch x4 + mask for step 0
    float x4v[2][4];
    int   mv[2];
#pragma unroll
    for (int r = 0; r < 2; ++r) {
        int p = tid + 256 * r;
        int b = p >> 3, jj = p & 7;
        const float* xp = g_x4 + ((size_t)0 * BB + b) * GG + jbase + jj;
        x4v[r][0] = xp[0];
        x4v[r][1] = xp[HH];
        x4v[r][2] = xp[2 * HH];
        x4v[r][3] = xp[3 * HH];
        mv[r] = mask[0 * BB + b];
    }

    for (int t = 0; t < TT; ++t) {
        if (w < 4) {
            // ================= MMA role: 64x32 over K-quarter ==========
            float acc[4][4][4];
#pragma unroll
            for (int mi = 0; mi < 4; ++mi)
#pragma unroll
                for (int nj = 0; nj < 4; ++nj)
#pragma unroll
                    for (int e = 0; e < 4; ++e) acc[mi][nj][e] = 0.f;

#pragma unroll 1
            for (int i = 0; i < 4; ++i) {
                const int cc = w + 4 * i;
                BAR_SYNC160(1 + w);                  // wait buffer w filled
#pragma unroll
                for (int g = 0; g < 4; ++g) {
                    uint32_t ah[4][4], al[4][4], bh[2][4], bl[2][4];
                    const uint32_t ka = (uint32_t)(g * 32);
#pragma unroll
                    for (int mi = 0; mi < 4; ++mi) {
                        LDSM_X4(ah[mi], aH_base + ka + (uint32_t)(mi * 16 * CH_ROW_B));
                        LDSM_X4(al[mi], aL_base + ka + (uint32_t)(mi * 16 * CH_ROW_B));
                    }
                    const uint32_t kb = (uint32_t)(cc * 128 + g * 32);
                    LDSM_X4(bh[0], bH_base + kb);
                    LDSM_X4(bh[1], bH_base + kb + (uint32_t)(16 * WH_ROW_B));
                    LDSM_X4(bl[0], bL_base + kb);
                    LDSM_X4(bl[1], bL_base + kb + (uint32_t)(16 * WH_ROW_B));
#pragma unroll
                    for (int mi = 0; mi < 4; ++mi) {
                        MMA_BF16(acc[mi][0], ah[mi], bh[0][0], bh[0][1]);
                        MMA_BF16(acc[mi][1], ah[mi], bh[0][2], bh[0][3]);
                        MMA_BF16(acc[mi][2], ah[mi], bh[1][0], bh[1][1]);
                        MMA_BF16(acc[mi][3], ah[mi], bh[1][2], bh[1][3]);
                        MMA_BF16(acc[mi][0], al[mi], bh[0][0], bh[0][1]);
                        MMA_BF16(acc[mi][1], al[mi], bh[0][2], bh[0][3]);
                        MMA_BF16(acc[mi][2], al[mi], bh[1][0], bh[1][1]);
                        MMA_BF16(acc[mi][3], al[mi], bh[1][2], bh[1][3]);
                        MMA_BF16(acc[mi][0], ah[mi], bl[0][0], bl[0][1]);
                        MMA_BF16(acc[mi][1], ah[mi], bl[0][2], bl[0][3]);
                        MMA_BF16(acc[mi][2], ah[mi], bl[1][0], bl[1][1]);
                        MMA_BF16(acc[mi][3], ah[mi], bl[1][2], bl[1][3]);
                    }
                }
                BAR_ARRIVE160(5 + w);                // buffer w consumed
            }

            // ---- park 64x32 fp32 partial in own (dead) buffer region
            {
                float* part = (float*)(sm + OFF_CH + w * CBUF_B);
                int rl = lane >> 2;
                int cb = (lane & 3) * 2;
#pragma unroll
                for (int mi = 0; mi < 4; ++mi) {
                    int row = mi * 16 + rl;
#pragma unroll
                    for (int nj = 0; nj < 4; ++nj) {
                        int col = nj * 8 + cb;
                        *(float2*)&part[row * PART_STRIDE + col] =
                            make_float2(acc[mi][nj][0], acc[mi][nj][1]);
                        *(float2*)&part[(row + 8) * PART_STRIDE + col] =
                            make_float2(acc[mi][nj][2], acc[mi][nj][3]);
                    }
                }
            }
        } else {
            // ================= staging role =================
            const uint4* csrc = (const uint4*)(g_cpk[t & 1]);  // [64][256] uint4
#pragma unroll 1
            for (int cc = 0; cc < NCH; ++cc) {
                const int buf = cc & 3;
                const uint4* cp = csrc + sr0 * 256 + cc * 16 + sk4;
                uint4 v[8];
#pragma unroll
                for (int i = 0; i < 8; ++i)
                    v[i] = __ldcg(cp + i * 8 * 256);

                if (!(t == 0 && cc < 4)) BAR_SYNC160(5 + buf);  // wait consumed

                char* chH = sm + OFF_CH + buf * CBUF_B;
                char* chL = sm + OFF_CL + buf * CBUF_B;
#pragma unroll
                for (int i = 0; i < 8; ++i) {
                    uint32_t o = sts_off + (uint32_t)(i * 8 * CH_ROW_B);
                    uint4 pv = v[i];
                    *(uint2*)(chH + o) =
                        make_uint2(__byte_perm(pv.x, pv.y, 0x7632),
                                   __byte_perm(pv.z, pv.w, 0x7632));
                    *(uint2*)(chL + o) =
                        make_uint2(__byte_perm(pv.x, pv.y, 0x5410),
                                   __byte_perm(pv.z, pv.w, 0x5410));
                }
                __threadfence_block();
                BAR_ARRIVE160(1 + buf);                          // filled
            }
        }

        __syncthreads();   // partials visible to everyone

        // ---- gates + state update + publish c (all 256 threads)
        unsigned* cdst = g_cpk[(t + 1) & 1];
        float hv[2];
#pragma unroll
        for (int r = 0; r < 2; ++r) {
            int p = tid + 256 * r;
            int b = p >> 3, jj = p & 7;
            int jcol = jbase + jj;

            float pi = x4v[r][0], pf = x4v[r][1];
            float po = x4v[r][2], pg = x4v[r][3];
#pragma unroll
            for (int w4 = 0; w4 < 4; ++w4) {
                const float* part =
                    (const float*)(sm + OFF_CH + w4 * CBUF_B) + b * PART_STRIDE;
                pi += part[jj];
                pf += part[8 + jj];
                po += part[16 + jj];
                pg += part[24 + jj];
            }

            float ig = 1.f / (1.f + __expf(-pi));
            float fg = 1.f / (1.f + __expf(-pf));
            float og = 1.f / (1.f + __expf(-po));
            float gg = tanhf(pg);

            float cold = csS[b * 8 + jj];
            float cnew = fg * cold + ig * gg;
            float hold = hsS[b * 8 + jj];
            int   m    = mv[r];
            float hnew = m ? (og * tanhf(cnew)) : hold;
            float cpub = m ? cnew : cold;

            hsS[b * 8 + jj] = hnew;
            csS[b * 8 + jj] = cpub;
            hv[r] = hnew;
            cdst[b * HH + jcol] = pack_split(cpub);
        }

        // ---- split-phase grid barrier: arrive, hide work, then wait
        __threadfence();
        __syncthreads();
        bar_target += gridDim.x;
        if (tid == 0) atomicAdd(&g_bar, 1u);

        // hidden work: write h outputs + prefetch next step's x4/mask
#pragma unroll
        for (int r = 0; r < 2; ++r) {
            int p = tid + 256 * r;
            int b = p >> 3, jj = p & 7;
            out[((size_t)t * BB + b) * HH + jbase + jj] = hv[r];
        }
        if (t + 1 < TT) {
#pragma unroll
            for (int r = 0; r < 2; ++r) {
                int p = tid + 256 * r;
                int b = p >> 3, jj = p & 7;
                const float* xp =
                    g_x4 + ((size_t)(t + 1) * BB + b) * GG + jbase + jj;
                x4v[r][0] = xp[0];
                x4v[r][1] = xp[HH];
                x4v[r][2] = xp[2 * HH];
                x4v[r][3] = xp[3 * HH];
                mv[r] = mask[(t + 1) * BB + b];
            }
        }

        if (tid == 0) {
            volatile unsigned* p = &g_bar;
            while (*p < bar_target) { __nanosleep(32); }
        }
        __syncthreads();
    }

    // ---- finals: h_last, c_last appended after hiddens
    const size_t hid_elems = (size_t)TT * BB * HH;
    for (int p = tid; p < 512; p += 256) {
        int b = p >> 3, jj = p & 7;
        out[hid_elems + b * HH + jbase + jj]           = hsS[b * 8 + jj];
        out[hid_elems + BB * HH + b * HH + jbase + jj] = csS[b * 8 + jj];
    }
}

// ------------------------------------------------------------------
// Launch
// ------------------------------------------------------------------
extern "C" void kernel_launch(void* const* d_in, const int* in_sizes, int n_in,
                              void* d_out, int out_size) {
    const float* X    = (const float*)d_in[0];
    const float* h0   = (const float*)d_in[1];
    const float* c0   = (const float*)d_in[2];
    const int*   mask = (const int*)d_in[3];
    const float* Wx   = (const float*)d_in[4];
    const float* Wh   = (const float*)d_in[5];
    const float* bias = (const float*)d_in[6];
    float* out = (float*)d_out;

    const int x4_smem = 4 * XTILE * 2;   // 73728 B
    cudaFuncSetAttribute(x4_mma_kernel,
                         cudaFuncAttributeMaxDynamicSharedMemorySize, x4_smem);
    cudaFuncSetAttribute(lstm_persistent,
                         cudaFuncAttributeMaxDynamicSharedMemorySize,
                         RSMEM_TOTAL);

    init_kernel<<<256, 256>>>(c0);

    split_x_kernel<<<(TT * BB * KIN / 4 + 255) / 256, 256>>>(X);
    split_w_kernel<<<(GG * KIN / 4 + 255) / 256, 256>>>(Wx);

    dim3 g(GG / 128, (TT * BB) / 128);   // (32, 256)
    x4_mma_kernel<<<g, 256, x4_smem>>>(bias);

    lstm_persistent<<<128, 256, RSMEM_TOTAL>>>(h0, c0, mask, Wh, out);
}

// round 17
// speedup vs baseline: 1.1156x; 1.1156x over previous
#include <cuda_runtime.h>
#include <cuda_bf16.h>
#include <math.h>
#include <stdint.h>

#define TT 512
#define BB 64
#define KIN 1024
#define HH 1024
#define GG 4096   // 4*H

// ------------------------------------------------------------------
// Scratch (device globals: allocation is forbidden in kernel_launch)
// ------------------------------------------------------------------
__device__ float         g_x4[(size_t)TT * BB * GG];     // 512 MB fp32: X@Wx^T + b
__device__ __nv_bfloat16 g_xh[(size_t)TT * BB * KIN];    // X hi split
__device__ __nv_bfloat16 g_xl[(size_t)TT * BB * KIN];    // X lo split
__device__ __nv_bfloat16 g_wxh[(size_t)GG * KIN];        // Wx hi
__device__ __nv_bfloat16 g_wxl[(size_t)GG * KIN];        // Wx lo
__device__ unsigned      g_cpk[2][BB * HH];              // packed (hi<<16)|lo cell state
__device__ unsigned      g_bar;                          // grid barrier counter

// ------------------------------------------------------------------
// helpers
// ------------------------------------------------------------------
__device__ __forceinline__ unsigned pack_split(float v) {
    __nv_bfloat16 h = __float2bfloat16_rn(v);
    float r = v - __bfloat162float(h);
    __nv_bfloat16 l = __float2bfloat16_rn(r);
    return ((unsigned)__bfloat16_as_ushort(h) << 16) |
           (unsigned)__bfloat16_as_ushort(l);
}

__device__ __forceinline__ uint32_t sh_addr(const void* p) {
    return (uint32_t)__cvta_generic_to_shared(p);
}

#define LDSM_X4(r, addr)                                                     \
    asm volatile("ldmatrix.sync.aligned.m8n8.x4.shared.b16 {%0,%1,%2,%3}, [%4];" \
                 : "=r"((r)[0]), "=r"((r)[1]), "=r"((r)[2]), "=r"((r)[3])    \
                 : "r"(addr))

#define MMA_BF16(d, a, b0, b1)                                               \
    asm volatile("mma.sync.aligned.m16n8k16.row.col.f32.bf16.bf16.f32 "      \
                 "{%0,%1,%2,%3}, {%4,%5,%6,%7}, {%8,%9}, {%0,%1,%2,%3};"     \
                 : "+f"((d)[0]), "+f"((d)[1]), "+f"((d)[2]), "+f"((d)[3])    \
                 : "r"((a)[0]), "r"((a)[1]), "r"((a)[2]), "r"((a)[3]),       \
                   "r"(b0), "r"(b1))

#define BAR_SYNC(id)                                                         \
    asm volatile("bar.sync %0, 256;" :: "r"(id) : "memory")
#define BAR_ARRIVE(id)                                                       \
    asm volatile("bar.arrive %0, 256;" :: "r"(id) : "memory")

// ------------------------------------------------------------------
// Init: barrier + seed packed c buffer
// ------------------------------------------------------------------
__global__ void init_kernel(const float* __restrict__ c0) {
    int idx = blockIdx.x * blockDim.x + threadIdx.x;
    if (idx == 0) g_bar = 0u;
    if (idx < BB * HH) g_cpk[0][idx] = pack_split(c0[idx]);
}

// ------------------------------------------------------------------
// Split kernels: fp32 -> (hi, lo) bf16
// ------------------------------------------------------------------
__device__ __forceinline__ void split4_store(const float4* src, uint2* dh,
                                             uint2* dl, int i) {
    float4 v = src[i];
    unsigned p0 = pack_split(v.x), p1 = pack_split(v.y);
    unsigned p2 = pack_split(v.z), p3 = pack_split(v.w);
    dh[i] = make_uint2(__byte_perm(p0, p1, 0x7632), __byte_perm(p2, p3, 0x7632));
    dl[i] = make_uint2(__byte_perm(p0, p1, 0x5410), __byte_perm(p2, p3, 0x5410));
}

__global__ void split_x_kernel(const float* __restrict__ X) {
    int i = blockIdx.x * blockDim.x + threadIdx.x;
    const int n4 = TT * BB * KIN / 4;
    if (i < n4)
        split4_store((const float4*)X, (uint2*)g_xh, (uint2*)g_xl, i);
}

__global__ void split_w_kernel(const float* __restrict__ W) {
    int i = blockIdx.x * blockDim.x + threadIdx.x;
    const int n4 = GG * KIN / 4;
    if (i < n4)
        split4_store((const float4*)W, (uint2*)g_wxh, (uint2*)g_wxl, i);
}

// ------------------------------------------------------------------
// X4 GEMM via tensor cores (R6-proven, unchanged)
// ------------------------------------------------------------------
#define XTILE (128 * 72)
#define XBUF_BYTES (XTILE * 2)

extern __shared__ char smem_raw[];

__global__ void __launch_bounds__(256) x4_mma_kernel(const float* __restrict__ bias) {
    __nv_bfloat16* SA = (__nv_bfloat16*)smem_raw;
    __nv_bfloat16* SB = SA + 2 * XTILE;

    const int tid  = threadIdx.x;
    const int lane = tid & 31;
    const int wid  = tid >> 5;
    const int wm   = wid >> 1;
    const int wn   = wid & 1;
    const int m0   = blockIdx.y * 128;
    const int n0   = blockIdx.x * 128;

    float acc[2][8][4];
#pragma unroll
    for (int mi = 0; mi < 2; ++mi)
#pragma unroll
        for (int nt = 0; nt < 8; ++nt)
#pragma unroll
            for (int e = 0; e < 4; ++e) acc[mi][nt][e] = 0.f;

    const uint32_t a_base =
        sh_addr(&SA[(wm * 32 + (lane & 15)) * 72 + (lane >> 4) * 8]);
    const uint32_t b_base =
        sh_addr(&SB[(wn * 64 + ((lane >> 4) << 3) + (lane & 7)) * 72 +
                    ((lane >> 3) & 1) * 8]);

    const int lrow = tid >> 3;
    const int lseg = tid & 7;

    uint4 av[4], bv[4];
#pragma unroll
    for (int j = 0; j < 4; ++j) {
        int row = lrow + 32 * j;
        av[j] = *(const uint4*)(g_xh  + (size_t)(m0 + row) * KIN + lseg * 8);
        bv[j] = *(const uint4*)(g_wxh + (size_t)(n0 + row) * KIN + lseg * 8);
    }
#pragma unroll
    for (int j = 0; j < 4; ++j) {
        int row = lrow + 32 * j;
        *(uint4*)&SA[row * 72 + lseg * 8] = av[j];
        *(uint4*)&SB[row * 72 + lseg * 8] = bv[j];
    }
    __syncthreads();

    for (int kc2 = 0; kc2 < 48; ++kc2) {
        const uint32_t boff = (uint32_t)((kc2 & 1) * XBUF_BYTES);

        if (kc2 < 47) {
            int nk = kc2 + 1;
            int p  = nk >> 4;
            int kb = (nk & 15) << 6;
            const __nv_bfloat16* Asrc = (p == 1) ? g_xl : g_xh;
            const __nv_bfloat16* Bsrc = (p == 2) ? g_wxl : g_wxh;
#pragma unroll
            for (int j = 0; j < 4; ++j) {
                int row = lrow + 32 * j;
                av[j] = *(const uint4*)(Asrc + (size_t)(m0 + row) * KIN + kb + lseg * 8);
                bv[j] = *(const uint4*)(Bsrc + (size_t)(n0 + row) * KIN + kb + lseg * 8);
            }
        }

#pragma unroll
        for (int ks = 0; ks < 4; ++ks) {
            uint32_t a[2][4];
            LDSM_X4(a[0], a_base + boff + (uint32_t)(ks * 16) * 2);
            LDSM_X4(a[1], a_base + boff + (uint32_t)(16 * 72 + ks * 16) * 2);
#pragma unroll
            for (int ntp = 0; ntp < 4; ++ntp) {
                uint32_t b4[4];
                LDSM_X4(b4, b_base + boff +
                            (uint32_t)(ntp * 16 * 72 + ks * 16) * 2);
#pragma unroll
                for (int mi = 0; mi < 2; ++mi) {
                    MMA_BF16(acc[mi][2 * ntp],     a[mi], b4[0], b4[1]);
                    MMA_BF16(acc[mi][2 * ntp + 1], a[mi], b4[2], b4[3]);
                }
            }
        }

        if (kc2 < 47) {
            __nv_bfloat16* SAd = SA + ((kc2 + 1) & 1) * XTILE;
            __nv_bfloat16* SBd = SB + ((kc2 + 1) & 1) * XTILE;
#pragma unroll
            for (int j = 0; j < 4; ++j) {
                int row = lrow + 32 * j;
                *(uint4*)&SAd[row * 72 + lseg * 8] = av[j];
                *(uint4*)&SBd[row * 72 + lseg * 8] = bv[j];
            }
        }
        __syncthreads();
    }

    const int r0  = m0 + wm * 32 + (lane >> 2);
    const int c0c = n0 + wn * 64 + (lane & 3) * 2;
#pragma unroll
    for (int nt = 0; nt < 8; ++nt) {
        float2 bv2 = *(const float2*)&bias[c0c + nt * 8];
#pragma unroll
        for (int mi = 0; mi < 2; ++mi) {
            float* o = g_x4 + (size_t)(r0 + mi * 16) * GG + c0c + nt * 8;
            float2 v0 = make_float2(acc[mi][nt][0] + bv2.x, acc[mi][nt][1] + bv2.y);
            float2 v1 = make_float2(acc[mi][nt][2] + bv2.x, acc[mi][nt][3] + bv2.y);
            *(float2*)o            = v0;
            *(float2*)(o + 8 * GG) = v1;
        }
    }
}

// ------------------------------------------------------------------
// Persistent recurrence kernel v6: warp-specialized, K-split WITHIN
// the R14-proven chunk pipeline.
// 128 CTAs x 256 threads.
//   Warps 0-3 (MMA): warp w computes the FULL 64x32 output over k16
//     slices {2w, 2w+1} of each k128 chunk (12 LDSM.X4 : 48 HMMA per
//     k16, zero fragment duplication). Partials summed in gate phase.
//   Warps 4-7 (staging): LDG packed c -> PRMT -> STS (double buffer,
//     identical to R14).
// Named barriers (count 256, R14-proven pairing):
//   filled[buf]:   id 1+buf  (staging arrive, MMA sync)
//   consumed[buf]: id 3+buf  (MMA arrive, staging sync)
// Partials parked in buf0 chunk regions (dead after last filled sync).
// ------------------------------------------------------------------
#define KC 128
#define NCHUNK (HH / KC)     // 8

// smem byte offsets
#define OFF_WHH  0                      // bf16 [32][1032]  66048
#define OFF_WHL  66048                  // bf16 [32][1032]  66048
#define OFF_CH   132096                 // bf16 [2][64][136] 34816
#define OFF_CL   166912                 // bf16 [2][64][136] 34816
#define OFF_HS   201728                 // float [64][8]     2048
#define OFF_CS   203776                 // float [64][8]     2048
#define RSMEM_TOTAL 205824

#define CBUF_BYTES (64 * 136 * 2)       // 17408 per buffer
#define WH_ROW_B   (1032 * 2)           // 2064
#define CH_ROW_B   (136 * 2)            // 272
#define PART_STRIDE 34                  // fp32 partial row stride (even)
#define PART_BYTES  (64 * PART_STRIDE * 4)   // 8704 per warp partial

__global__ void __launch_bounds__(256, 1) lstm_persistent(
    const float* __restrict__ h0, const float* __restrict__ c0,
    const int* __restrict__ mask, const float* __restrict__ Wh,
    float* __restrict__ out)
{
    const int tid   = threadIdx.x;
    const int lane  = tid & 31;
    const int w     = tid >> 5;      // warp 0..7
    const int ci    = blockIdx.x;
    const int jbase = ci * 8;

    char* sm = smem_raw;
    const uint32_t smem_base = sh_addr(sm);
    __nv_bfloat16* whH = (__nv_bfloat16*)(sm + OFF_WHH);
    __nv_bfloat16* whL = (__nv_bfloat16*)(sm + OFF_WHL);
    float* hsS  = (float*)(sm + OFF_HS);
    float* csS  = (float*)(sm + OFF_CS);

    // ---- load Wh slice, split to bf16 hi/lo (resident all steps)
    for (int i = 0; i < 128; ++i) {
        int e = i * 256 + tid;           // 32768 elements
        int n = e >> 10, k = e & 1023;
        int grow = (n >> 3) * HH + jbase + (n & 7);
        float v = Wh[(size_t)grow * HH + k];
        __nv_bfloat16 h = __float2bfloat16_rn(v);
        float r = v - __bfloat162float(h);
        whH[n * 1032 + k] = h;
        whL[n * 1032 + k] = __float2bfloat16_rn(r);
    }
    // ---- init h / own-c state
    for (int p = tid; p < 512; p += 256) {
        int b = p >> 3, jj = p & 7;
        hsS[b * 8 + jj] = h0[b * HH + jbase + jj];
        csS[b * 8 + jj] = c0[b * HH + jbase + jj];
    }
    __syncthreads();

    // ---- MMA-warp addressing (warps 0-3): full-m A, full-n B
    const uint32_t aH_base = smem_base + OFF_CH +
        (uint32_t)((lane & 15) * CH_ROW_B + (lane >> 4) * 16);
    const uint32_t aL_base = aH_base + (OFF_CL - OFF_CH);
    const uint32_t bH_base = smem_base + OFF_WHH +
        (uint32_t)((((lane >> 4) << 3) + (lane & 7)) * WH_ROW_B +
                   ((lane >> 3) & 1) * 16);
    const uint32_t bL_base = bH_base + (OFF_WHL - OFF_WHH);
    // partial parking region: buf0 halves of CH / CL (dead by park time)
    float* partMy = (float*)(sm + OFF_CH + ((w >> 1) & 1) * (OFF_CL - OFF_CH) +
                             (w & 1) * PART_BYTES);

    // ---- staging-warp addressing (warps 4-7)
    const int tid2 = tid - 128;              // 0..127 for staging threads
    const int r0   = (tid2 >> 5) & 3;        // base row 0..3
    const int k4   = tid2 & 31;              // uint4 index within chunk row
    const uint32_t sts_base = (uint32_t)(r0 * CH_ROW_B + k4 * 8);

    unsigned bar_target = 0;

    // ---- prefetch x4 + mask for step 0
    float x4v[2][4];
    int   mv[2];
#pragma unroll
    for (int r = 0; r < 2; ++r) {
        int p = tid + 256 * r;
        int b = p >> 3, jj = p & 7;
        const float* xp = g_x4 + ((size_t)0 * BB + b) * GG + jbase + jj;
        x4v[r][0] = xp[0];
        x4v[r][1] = xp[HH];
        x4v[r][2] = xp[2 * HH];
        x4v[r][3] = xp[3 * HH];
        mv[r] = mask[0 * BB + b];
    }

    for (int t = 0; t < TT; ++t) {
        if (w < 4) {
            // ===== MMA role: full 64x32 over k16 slices {2w, 2w+1} =====
            float acc[4][4][4];
#pragma unroll
            for (int mi = 0; mi < 4; ++mi)
#pragma unroll
                for (int nj = 0; nj < 4; ++nj)
#pragma unroll
                    for (int e = 0; e < 4; ++e) acc[mi][nj][e] = 0.f;

#pragma unroll 1
            for (int kc = 0; kc < NCHUNK; ++kc) {
                const int buf = kc & 1;
                BAR_SYNC(1 + buf);                      // wait filled
                const uint32_t ab = (uint32_t)(buf * CBUF_BYTES);
#pragma unroll
                for (int g = 0; g < 2; ++g) {
                    const int s = 2 * w + g;            // k16 slice in chunk
                    uint32_t ah[4][4], al[4][4], bh[2][4], bl[2][4];
                    const uint32_t ka = ab + (uint32_t)(s * 32);
#pragma unroll
                    for (int mi = 0; mi < 4; ++mi) {
                        LDSM_X4(ah[mi], aH_base + ka + (uint32_t)(mi * 16 * CH_ROW_B));
                        LDSM_X4(al[mi], aL_base + ka + (uint32_t)(mi * 16 * CH_ROW_B));
                    }
                    const uint32_t kb = (uint32_t)(kc * 256 + s * 32);
                    LDSM_X4(bh[0], bH_base + kb);
                    LDSM_X4(bh[1], bH_base + kb + (uint32_t)(16 * WH_ROW_B));
                    LDSM_X4(bl[0], bL_base + kb);
                    LDSM_X4(bl[1], bL_base + kb + (uint32_t)(16 * WH_ROW_B));
#pragma unroll
                    for (int mi = 0; mi < 4; ++mi) {
                        MMA_BF16(acc[mi][0], ah[mi], bh[0][0], bh[0][1]);
                        MMA_BF16(acc[mi][1], ah[mi], bh[0][2], bh[0][3]);
                        MMA_BF16(acc[mi][2], ah[mi], bh[1][0], bh[1][1]);
                        MMA_BF16(acc[mi][3], ah[mi], bh[1][2], bh[1][3]);
                        MMA_BF16(acc[mi][0], al[mi], bh[0][0], bh[0][1]);
                        MMA_BF16(acc[mi][1], al[mi], bh[0][2], bh[0][3]);
                        MMA_BF16(acc[mi][2], al[mi], bh[1][0], bh[1][1]);
                        MMA_BF16(acc[mi][3], al[mi], bh[1][2], bh[1][3]);
                        MMA_BF16(acc[mi][0], ah[mi], bl[0][0], bl[0][1]);
                        MMA_BF16(acc[mi][1], ah[mi], bl[0][2], bl[0][3]);
                        MMA_BF16(acc[mi][2], ah[mi], bl[1][0], bl[1][1]);
                        MMA_BF16(acc[mi][3], ah[mi], bl[1][2], bl[1][3]);
                    }
                }
                BAR_ARRIVE(3 + buf);                    // signal consumed
            }

            // ---- park 64x32 fp32 partial (buf0 region: dead by now —
            //      all MMA warps passed the chunk-7 filled sync)
            {
                int rl = lane >> 2;
                int cb = (lane & 3) * 2;
#pragma unroll
                for (int mi = 0; mi < 4; ++mi) {
                    int row = mi * 16 + rl;
#pragma unroll
                    for (int nj = 0; nj < 4; ++nj) {
                        int col = nj * 8 + cb;
                        *(float2*)&partMy[row * PART_STRIDE + col] =
                            make_float2(acc[mi][nj][0], acc[mi][nj][1]);
                        *(float2*)&partMy[(row + 8) * PART_STRIDE + col] =
                            make_float2(acc[mi][nj][2], acc[mi][nj][3]);
                    }
                }
            }
        } else {
            // ================= staging role (R14-identical) ============
            const uint4* csrc = (const uint4*)(g_cpk[t & 1]);
#pragma unroll 1
            for (int kc = 0; kc < NCHUNK; ++kc) {
                const int buf = kc & 1;
                const uint4* cp = csrc + r0 * 256 + kc * 32 + k4;
                uint4 va[4], vb[4];
#pragma unroll
                for (int i = 0; i < 4; ++i) va[i] = __ldcg(cp + i * 1024);
#pragma unroll
                for (int i = 0; i < 4; ++i) vb[i] = __ldcg(cp + (4 + i) * 1024);

                if (!(t == 0 && kc < 2)) BAR_SYNC(3 + buf);   // wait consumed

                char* chH = sm + OFF_CH + buf * CBUF_BYTES;
                char* chL = sm + OFF_CL + buf * CBUF_BYTES;

#pragma unroll
                for (int i = 0; i < 4; ++i) {
                    uint32_t o = sts_base + (uint32_t)(i * 4 * CH_ROW_B);
                    uint4 pv = va[i];
                    *(uint2*)(chH + o) = make_uint2(__byte_perm(pv.x, pv.y, 0x7632),
                                                    __byte_perm(pv.z, pv.w, 0x7632));
                    *(uint2*)(chL + o) = make_uint2(__byte_perm(pv.x, pv.y, 0x5410),
                                                    __byte_perm(pv.z, pv.w, 0x5410));
                }
#pragma unroll
                for (int i = 0; i < 4; ++i) va[i] = __ldcg(cp + (8 + i) * 1024);
#pragma unroll
                for (int i = 0; i < 4; ++i) {
                    uint32_t o = sts_base + (uint32_t)((4 + i) * 4 * CH_ROW_B);
                    uint4 pv = vb[i];
                    *(uint2*)(chH + o) = make_uint2(__byte_perm(pv.x, pv.y, 0x7632),
                                                    __byte_perm(pv.z, pv.w, 0x7632));
                    *(uint2*)(chL + o) = make_uint2(__byte_perm(pv.x, pv.y, 0x5410),
                                                    __byte_perm(pv.z, pv.w, 0x5410));
                }
#pragma unroll
                for (int i = 0; i < 4; ++i) vb[i] = __ldcg(cp + (12 + i) * 1024);
#pragma unroll
                for (int i = 0; i < 4; ++i) {
                    uint32_t o = sts_base + (uint32_t)((8 + i) * 4 * CH_ROW_B);
                    uint4 pv = va[i];
                    *(uint2*)(chH + o) = make_uint2(__byte_perm(pv.x, pv.y, 0x7632),
                                                    __byte_perm(pv.z, pv.w, 0x7632));
                    *(uint2*)(chL + o) = make_uint2(__byte_perm(pv.x, pv.y, 0x5410),
                                                    __byte_perm(pv.z, pv.w, 0x5410));
                }
#pragma unroll
                for (int i = 0; i < 4; ++i) {
                    uint32_t o = sts_base + (uint32_t)((12 + i) * 4 * CH_ROW_B);
                    uint4 pv = vb[i];
                    *(uint2*)(chH + o) = make_uint2(__byte_perm(pv.x, pv.y, 0x7632),
                                                    __byte_perm(pv.z, pv.w, 0x7632));
                    *(uint2*)(chL + o) = make_uint2(__byte_perm(pv.x, pv.y, 0x5410),
                                                    __byte_perm(pv.z, pv.w, 0x5410));
                }

                __threadfence_block();
                BAR_ARRIVE(1 + buf);                    // signal filled
            }
        }

        __syncthreads();   // partials visible to everyone

        // ---- gates + state update + publish c (all 256 threads)
        unsigned* cdst = g_cpk[(t + 1) & 1];
        float hv[2];
#pragma unroll
        for (int r = 0; r < 2; ++r) {
            int p = tid + 256 * r;
            int b = p >> 3, jj = p & 7;
            int jcol = jbase + jj;

            float pi = x4v[r][0], pf = x4v[r][1];
            float po = x4v[r][2], pg = x4v[r][3];
#pragma unroll
            for (int w4 = 0; w4 < 4; ++w4) {
                const float* part =
                    (const float*)(sm + OFF_CH +
                                   ((w4 >> 1) & 1) * (OFF_CL - OFF_CH) +
                                   (w4 & 1) * PART_BYTES) + b * PART_STRIDE;
                pi += part[jj];
                pf += part[8 + jj];
                po += part[16 + jj];
                pg += part[24 + jj];
            }

            float ig = 1.f / (1.f + __expf(-pi));
            float fg = 1.f / (1.f + __expf(-pf));
            float og = 1.f / (1.f + __expf(-po));
            float gg = tanhf(pg);

            float cold = csS[b * 8 + jj];
            float cnew = fg * cold + ig * gg;
            float hold = hsS[b * 8 + jj];
            int   m    = mv[r];
            float hnew = m ? (og * tanhf(cnew)) : hold;
            float cpub = m ? cnew : cold;

            hsS[b * 8 + jj] = hnew;
            csS[b * 8 + jj] = cpub;
            hv[r] = hnew;
            cdst[b * HH + jcol] = pack_split(cpub);
        }

        // ---- split-phase grid barrier: arrive, hide work, then wait
        __threadfence();
        __syncthreads();
        bar_target += gridDim.x;
        if (tid == 0) atomicAdd(&g_bar, 1u);

        // hidden work: write h outputs + prefetch next step's x4/mask
#pragma unroll
        for (int r = 0; r < 2; ++r) {
            int p = tid + 256 * r;
            int b = p >> 3, jj = p & 7;
            out[((size_t)t * BB + b) * HH + jbase + jj] = hv[r];
        }
        if (t + 1 < TT) {
#pragma unroll
            for (int r = 0; r < 2; ++r) {
                int p = tid + 256 * r;
                int b = p >> 3, jj = p & 7;
                const float* xp =
                    g_x4 + ((size_t)(t + 1) * BB + b) * GG + jbase + jj;
                x4v[r][0] = xp[0];
                x4v[r][1] = xp[HH];
                x4v[r][2] = xp[2 * HH];
                x4v[r][3] = xp[3 * HH];
                mv[r] = mask[(t + 1) * BB + b];
            }
        }

        if (tid == 0) {
            volatile unsigned* p = &g_bar;
            while (*p < bar_target) { __nanosleep(32); }
        }
        __syncthreads();
    }

    // ---- finals: h_last, c_last appended after hiddens
    const size_t hid_elems = (size_t)TT * BB * HH;
    for (int p = tid; p < 512; p += 256) {
        int b = p >> 3, jj = p & 7;
        out[hid_elems + b * HH + jbase + jj]           = hsS[b * 8 + jj];
        out[hid_elems + BB * HH + b * HH + jbase + jj] = csS[b * 8 + jj];
    }
}

// ------------------------------------------------------------------
// Launch
// ------------------------------------------------------------------
extern "C" void kernel_launch(void* const* d_in, const int* in_sizes, int n_in,
                              void* d_out, int out_size) {
    const float* X    = (const float*)d_in[0];
    const float* h0   = (const float*)d_in[1];
    const float* c0   = (const float*)d_in[2];
    const int*   mask = (const int*)d_in[3];
    const float* Wx   = (const float*)d_in[4];
    const float* Wh   = (const float*)d_in[5];
    const float* bias = (const float*)d_in[6];
    float* out = (float*)d_out;

    const int x4_smem = 4 * XTILE * 2;   // 73728 B
    cudaFuncSetAttribute(x4_mma_kernel,
                         cudaFuncAttributeMaxDynamicSharedMemorySize, x4_smem);
    cudaFuncSetAttribute(lstm_persistent,
                         cudaFuncAttributeMaxDynamicSharedMemorySize,
                         RSMEM_TOTAL);

    init_kernel<<<256, 256>>>(c0);

    split_x_kernel<<<(TT * BB * KIN / 4 + 255) / 256, 256>>>(X);
    split_w_kernel<<<(GG * KIN / 4 + 255) / 256, 256>>>(Wx);

    dim3 g(GG / 128, (TT * BB) / 128);   // (32, 256)
    x4_mma_kernel<<<g, 256, x4_smem>>>(bias);

    lstm_persistent<<<128, 256, RSMEM_TOTAL>>>(h0, c0, mask, Wh, out);
}